// round 11
// baseline (speedup 1.0000x reference)
#include <cuda_runtime.h>
#include <cuda_bf16.h>
#include <cstdint>

// Problem constants
#define MAXN 100000
#define MAXE 600000
#define D 128
#define L_LAYERS 5
#define NPART 296
#define SCAN_BLK 1024

// ---------------- scratch (device globals; no allocation allowed) -------------
__device__ float g_bufA[MAXN * D];
__device__ float g_bufB[MAXN * D];
__device__ int   g_deg[MAXN];
__device__ int   g_rowptr[MAXN + 1];
__device__ int   g_cursor[MAXN];
__device__ int   g_col[MAXE];
__device__ float g_part[NPART * D];
__device__ int   g_bsum[128];
__device__ int   g_boff[128];
// pre-split transposed weights: 10 matrices x 128x128 bf16 (as uint4)
__device__ uint4 g_WhiT[10 * 128 * 128 / 8];
__device__ uint4 g_WloT[10 * 128 * 128 / 8];

// ---------------- utility kernels --------------------------------------------
__global__ void k_zero_int(int* __restrict__ p, int n) {
    int i = blockIdx.x * blockDim.x + threadIdx.x;
    if (i < n) p[i] = 0;
}

__global__ void k_gather(const int* __restrict__ x, const float* __restrict__ emb,
                         float* __restrict__ h, int n) {
    int i = blockIdx.x * blockDim.x + threadIdx.x;
    if (i < n * (D / 4)) {
        int node = i >> 5;
        int q    = i & 31;
        reinterpret_cast<float4*>(h)[(size_t)node * 32 + q] =
            reinterpret_cast<const float4*>(emb)[(size_t)x[node] * 32 + q];
    }
}

__global__ void k_count(const int* __restrict__ dst, int* __restrict__ deg, int e) {
    int i = blockIdx.x * blockDim.x + threadIdx.x;
    if (i < e) atomicAdd(&deg[dst[i]], 1);
}

// split + transpose weights: WT[n][k] = split(W[k][n]); 40 blocks (mat, k-quarter)
__global__ void k_wsplit(const float* __restrict__ Wa, const float* __restrict__ Wb,
                         __nv_bfloat16* __restrict__ hi, __nv_bfloat16* __restrict__ lo) {
    int mat = blockIdx.x >> 2, kq = blockIdx.x & 3;
    const float* W = (mat < 5) ? (Wa + mat * 16384) : (Wb + (mat - 5) * 16384);
    __nv_bfloat16* H  = hi + mat * 16384;
    __nv_bfloat16* Lo = lo + mat * 16384;
    int nidx = threadIdx.x;
    for (int k = kq * 32; k < kq * 32 + 32; k++) {
        float x = W[k * 128 + nidx];
        __nv_bfloat16 h = __float2bfloat16(x);
        H[nidx * 128 + k]  = h;
        Lo[nidx * 128 + k] = __float2bfloat16(x - __bfloat162float(h));
    }
}

// ---- 3-phase scan -------------------------------------------------------------
__global__ void k_scan_blk(const int* __restrict__ deg, int* __restrict__ rowptr,
                           int* __restrict__ bsum, int n) {
    int i = blockIdx.x * SCAN_BLK + threadIdx.x;
    int lane = threadIdx.x & 31, wid = threadIdx.x >> 5;
    int v = (i < n) ? deg[i] : 0;
    int inc = v;
#pragma unroll
    for (int o = 1; o < 32; o <<= 1) {
        int t = __shfl_up_sync(0xFFFFFFFFu, inc, o);
        if (lane >= o) inc += t;
    }
    __shared__ int wsum[32];
    if (lane == 31) wsum[wid] = inc;
    __syncthreads();
    if (wid == 0) {
        int s = wsum[lane];
#pragma unroll
        for (int o = 1; o < 32; o <<= 1) {
            int t = __shfl_up_sync(0xFFFFFFFFu, s, o);
            if (lane >= o) s += t;
        }
        wsum[lane] = s;
    }
    __syncthreads();
    int base = (wid > 0) ? wsum[wid - 1] : 0;
    if (i < n) rowptr[i] = base + inc - v;
    if (threadIdx.x == SCAN_BLK - 1) bsum[blockIdx.x] = base + inc;
}

__global__ void k_scan_top(const int* __restrict__ bsum, int* __restrict__ boff,
                           int* __restrict__ total_out, int nb) {
    int t = threadIdx.x, lane = t & 31, wid = t >> 5;
    int v = (t < nb) ? bsum[t] : 0;
    int inc = v;
#pragma unroll
    for (int o = 1; o < 32; o <<= 1) {
        int u = __shfl_up_sync(0xFFFFFFFFu, inc, o);
        if (lane >= o) inc += u;
    }
    __shared__ int ws[32];
    __shared__ int wsx[33];
    if (lane == 31) ws[wid] = inc;
    __syncthreads();
    if (t == 0) {
        wsx[0] = 0;
        for (int w = 0; w < 4; w++) wsx[w + 1] = wsx[w] + ws[w];
    }
    __syncthreads();
    int excl = wsx[wid] + inc - v;
    if (t < nb) boff[t] = excl;
    if (t == blockDim.x - 1) *total_out = wsx[4];
}

__global__ void k_scan_add(int* __restrict__ rowptr, int* __restrict__ cursor,
                           const int* __restrict__ boff, int n) {
    int i = blockIdx.x * blockDim.x + threadIdx.x;
    if (i < n) {
        int r = rowptr[i] + boff[i >> 10];
        rowptr[i] = r;
        cursor[i] = r;
    }
}

__global__ void k_scatter(const int* __restrict__ src, const int* __restrict__ dst,
                          int* __restrict__ cursor, int* __restrict__ col, int e) {
    int i = blockIdx.x * blockDim.x + threadIdx.x;
    if (i < e) {
        int d = dst[i];
        int p = atomicAdd(&cursor[d], 1);
        col[p] = src[i];
    }
}

// ---------------- fused (agg?) + mma.sync GEMM: C = relu((Z [+agg]) @ W + b) --
// Block tile 256x128, 8 warps (4m x 2n), warp tile 64x64, K=128.
// Split-bf16: 3 HMMA terms. SMEM bf16 row stride 272 B.
#define TSTR   272
#define SM_ZHI 0
#define SM_ZLO (256 * TSTR)                 // 69632
#define SM_WHI (2 * 256 * TSTR)             // 139264
#define SM_WLO (SM_WHI + 128 * TSTR)        // 174080
#define SM_BIAS (SM_WLO + 128 * TSTR)       // 208896
#define SMEM_MMA (SM_BIAS + 512)            // 209408

__device__ __forceinline__ uint32_t smem_u32(const void* p) {
    uint32_t a;
    asm("{ .reg .u64 t; cvta.to.shared.u64 t, %1; cvt.u32.u64 %0, t; }" : "=r"(a) : "l"(p));
    return a;
}
__device__ __forceinline__ void ldsm_x4(uint32_t* r, uint32_t addr) {
    asm volatile("ldmatrix.sync.aligned.m8n8.x4.shared.b16 {%0,%1,%2,%3}, [%4];"
        : "=r"(r[0]), "=r"(r[1]), "=r"(r[2]), "=r"(r[3]) : "r"(addr));
}
__device__ __forceinline__ void mma_16816(float* c, const uint32_t* a, const uint32_t* b) {
    asm volatile(
        "mma.sync.aligned.m16n8k16.row.col.f32.bf16.bf16.f32 "
        "{%0,%1,%2,%3}, {%4,%5,%6,%7}, {%8,%9}, {%0,%1,%2,%3};"
        : "+f"(c[0]), "+f"(c[1]), "+f"(c[2]), "+f"(c[3])
        : "r"(a[0]), "r"(a[1]), "r"(a[2]), "r"(a[3]), "r"(b[0]), "r"(b[1]));
}
__device__ __forceinline__ uint32_t pack_bf16x2(float a, float b) {
    __nv_bfloat162 t = __floats2bfloat162_rn(a, b);
    return *reinterpret_cast<uint32_t*>(&t);
}
__device__ __forceinline__ void cp_async16(uint32_t saddr, const void* gptr) {
    asm volatile("cp.async.ca.shared.global [%0], [%1], 16;" :: "r"(saddr), "l"(gptr));
}

__global__ __launch_bounds__(256, 1)
void k_gemm_mma(const float* __restrict__ Z,
                const uint4* __restrict__ WhiT, const uint4* __restrict__ WloT,
                const float* __restrict__ bias, float* __restrict__ C,
                const int* __restrict__ rowptr, const int* __restrict__ col,
                int agg, int n) {
    extern __shared__ char sm[];
    const uint32_t sb = smem_u32(sm);
    const int tid = threadIdx.x;
    const int lane = tid & 31, w = tid >> 5;
    const int rowBase = blockIdx.x * 256;

    // ---- W tiles via cp.async (overlaps with Z/agg staging below) ----
    {
#pragma unroll
        for (int it = 0; it < 8; it++) {
            int j = tid + it * 256;          // 0..2047
            int row = j >> 4, chunk = j & 15;
            uint32_t dofs = row * TSTR + chunk * 16;
            cp_async16(sb + SM_WHI + dofs, WhiT + row * 16 + chunk);
            cp_async16(sb + SM_WLO + dofs, WloT + row * 16 + chunk);
        }
        asm volatile("cp.async.commit_group;" ::: "memory");
    }
    if (tid < 128) reinterpret_cast<float*>(sm + SM_BIAS)[tid] = bias[tid];

    // ---- Z staging (+ optional CSR aggregation), warp = 32 rows ----
    {
        const float4* h4 = reinterpret_cast<const float4*>(Z);
        for (int lr = 0; lr < 32; lr++) {
            int row = w * 32 + lr;
            int gr = rowBase + row;
            float4 a4 = make_float4(0.f, 0.f, 0.f, 0.f);
            if (gr < n) {
                a4 = __ldg(&h4[(size_t)gr * 32 + lane]);
                if (agg) {
                    int s0 = __ldg(&rowptr[gr]), s1 = __ldg(&rowptr[gr + 1]);
                    int j = s0;
                    for (; j + 1 < s1; j += 2) {
                        int c0 = __ldg(&col[j]), c1 = __ldg(&col[j + 1]);
                        float4 v0 = __ldg(&h4[(size_t)c0 * 32 + lane]);
                        float4 v1 = __ldg(&h4[(size_t)c1 * 32 + lane]);
                        a4.x += v0.x + v1.x; a4.y += v0.y + v1.y;
                        a4.z += v0.z + v1.z; a4.w += v0.w + v1.w;
                    }
                    if (j < s1) {
                        int c0 = __ldg(&col[j]);
                        float4 v0 = __ldg(&h4[(size_t)c0 * 32 + lane]);
                        a4.x += v0.x; a4.y += v0.y; a4.z += v0.z; a4.w += v0.w;
                    }
                }
            }
            uint2 hp, lp;
            hp.x = pack_bf16x2(a4.x, a4.y);
            hp.y = pack_bf16x2(a4.z, a4.w);
            float lx = a4.x - __bfloat162float(__float2bfloat16(a4.x));
            float ly = a4.y - __bfloat162float(__float2bfloat16(a4.y));
            float lz = a4.z - __bfloat162float(__float2bfloat16(a4.z));
            float lw = a4.w - __bfloat162float(__float2bfloat16(a4.w));
            lp.x = pack_bf16x2(lx, ly);
            lp.y = pack_bf16x2(lz, lw);
            *reinterpret_cast<uint2*>(sm + SM_ZHI + row * TSTR + lane * 8) = hp;
            *reinterpret_cast<uint2*>(sm + SM_ZLO + row * TSTR + lane * 8) = lp;
        }
    }
    asm volatile("cp.async.wait_group 0;" ::: "memory");
    __syncthreads();

    // ---- compute: warp tile 64x64 at (m0, n0) ----
    const int m0 = (w >> 1) * 64, n0 = (w & 1) * 64;
    float acc[4][8][4];
#pragma unroll
    for (int a = 0; a < 4; a++)
#pragma unroll
        for (int b = 0; b < 8; b++)
#pragma unroll
            for (int c = 0; c < 4; c++) acc[a][b][c] = 0.f;

    const uint32_t a_row  = m0 + (lane & 15);
    const uint32_t a_coff = (lane >> 4) * 8;
    const uint32_t b_row  = n0 + ((lane >> 4) << 3) + (lane & 7);
    const uint32_t b_coff = ((lane >> 3) & 1) * 8;

#pragma unroll
    for (int ks = 0; ks < 8; ks++) {
        const int k = ks * 16;
        uint32_t ah[4][4], al[4][4];
#pragma unroll
        for (int mf = 0; mf < 4; mf++) {
            uint32_t addr = sb + SM_ZHI + (a_row + mf * 16) * TSTR + (k + a_coff) * 2;
            ldsm_x4(ah[mf], addr);
            ldsm_x4(al[mf], addr + (SM_ZLO - SM_ZHI));
        }
#pragma unroll
        for (int nfg = 0; nfg < 4; nfg++) {
            uint32_t baddr = sb + SM_WHI + (b_row + nfg * 16) * TSTR + (k + b_coff) * 2;
            uint32_t bh[4], bl[4];
            ldsm_x4(bh, baddr);
            ldsm_x4(bl, baddr + (SM_WLO - SM_WHI));
#pragma unroll
            for (int mf = 0; mf < 4; mf++) {
                mma_16816(acc[mf][nfg * 2 + 0], ah[mf], bh + 0);
                mma_16816(acc[mf][nfg * 2 + 0], al[mf], bh + 0);
                mma_16816(acc[mf][nfg * 2 + 0], ah[mf], bl + 0);
                mma_16816(acc[mf][nfg * 2 + 1], ah[mf], bh + 2);
                mma_16816(acc[mf][nfg * 2 + 1], al[mf], bh + 2);
                mma_16816(acc[mf][nfg * 2 + 1], ah[mf], bl + 2);
            }
        }
    }

    // ---- epilogue: bias + relu, float2 stores ----
    const float* bs = reinterpret_cast<const float*>(sm + SM_BIAS);
#pragma unroll
    for (int mf = 0; mf < 4; mf++) {
#pragma unroll
        for (int nf = 0; nf < 8; nf++) {
            int r = m0 + mf * 16 + (lane >> 2);
            int c = n0 + nf * 8 + (lane & 3) * 2;
            float b0 = bs[c], b1 = bs[c + 1];
            int gr0 = rowBase + r;
            if (gr0 < n) {
                float2 v;
                v.x = fmaxf(acc[mf][nf][0] + b0, 0.f);
                v.y = fmaxf(acc[mf][nf][1] + b1, 0.f);
                *reinterpret_cast<float2*>(C + (size_t)gr0 * 128 + c) = v;
            }
            int gr1 = gr0 + 8;
            if (gr1 < n) {
                float2 v;
                v.x = fmaxf(acc[mf][nf][2] + b0, 0.f);
                v.y = fmaxf(acc[mf][nf][3] + b1, 0.f);
                *reinterpret_cast<float2*>(C + (size_t)gr1 * 128 + c) = v;
            }
        }
    }
}

// ---------------- pool + final -------------------------------------------------
__global__ void k_pool_partial(const float* __restrict__ h, float* __restrict__ part, int n) {
    int d = threadIdx.x;
    float acc = 0.f;
    for (int r = blockIdx.x; r < n; r += gridDim.x)
        acc += h[(size_t)r * D + d];
    part[blockIdx.x * D + d] = acc;
}

__global__ void k_final(const float* __restrict__ part, const float* __restrict__ Wlin,
                        const float* __restrict__ blin, float* __restrict__ out) {
    __shared__ float pooled[D];
    int t = threadIdx.x;
    float acc = 0.f;
    for (int p = 0; p < NPART; p++) acc += part[p * D + t];
    pooled[t] = acc;
    __syncthreads();
    float o = blin[t];
    for (int d = 0; d < D; d++) o = fmaf(pooled[d], Wlin[d * D + t], o);
    out[t] = o;
}

// ---------------- launch -------------------------------------------------------
extern "C" void kernel_launch(void* const* d_in, const int* in_sizes, int n_in,
                              void* d_out, int out_size) {
    const int*   x    = (const int*)d_in[0];
    const int*   ei   = (const int*)d_in[1];
    const float* emb  = (const float*)d_in[2];
    const float* Wa   = (const float*)d_in[3];
    const float* ba   = (const float*)d_in[4];
    const float* Wb   = (const float*)d_in[5];
    const float* bb   = (const float*)d_in[6];
    const float* Wlin = (const float*)d_in[7];
    const float* blin = (const float*)d_in[8];
    float* out = (float*)d_out;

    const int N = in_sizes[0];
    const int E = in_sizes[1] / 2;
    const int* src = ei;
    const int* dst = ei + E;

    float *A, *B, *part;
    int *deg, *rowptr, *cursor, *col, *bsum, *boff;
    uint4 *whi, *wlo;
    cudaGetSymbolAddress((void**)&A, g_bufA);
    cudaGetSymbolAddress((void**)&B, g_bufB);
    cudaGetSymbolAddress((void**)&deg, g_deg);
    cudaGetSymbolAddress((void**)&rowptr, g_rowptr);
    cudaGetSymbolAddress((void**)&cursor, g_cursor);
    cudaGetSymbolAddress((void**)&col, g_col);
    cudaGetSymbolAddress((void**)&part, g_part);
    cudaGetSymbolAddress((void**)&bsum, g_bsum);
    cudaGetSymbolAddress((void**)&boff, g_boff);
    cudaGetSymbolAddress((void**)&whi, g_WhiT);
    cudaGetSymbolAddress((void**)&wlo, g_WloT);

    cudaFuncSetAttribute(k_gemm_mma, cudaFuncAttributeMaxDynamicSharedMemorySize, SMEM_MMA);

    // h = emb[x]
    k_gather<<<(N * 32 + 255) / 256, 256>>>(x, emb, A, N);

    // pre-split weights to transposed bf16 hi/lo
    k_wsplit<<<40, 128>>>(Wa, Wb, (__nv_bfloat16*)whi, (__nv_bfloat16*)wlo);

    // CSR build
    k_zero_int<<<(N + 255) / 256, 256>>>(deg, N);
    k_count<<<(E + 255) / 256, 256>>>(dst, deg, E);
    const int nb = (N + SCAN_BLK - 1) / SCAN_BLK;
    k_scan_blk<<<nb, SCAN_BLK>>>(deg, rowptr, bsum, N);
    k_scan_top<<<1, 128>>>(bsum, boff, rowptr + N, nb);
    k_scan_add<<<(N + 255) / 256, 256>>>(rowptr, cursor, boff, N);
    k_scatter<<<(E + 255) / 256, 256>>>(src, dst, cursor, col, E);

    const int gemm_blocks = (N + 255) / 256;
    for (int l = 0; l < L_LAYERS; l++) {
        // GEMM 1: fused aggregation (z = h + sum neighbors), A -> B
        k_gemm_mma<<<gemm_blocks, 256, SMEM_MMA>>>(A, whi + (size_t)l * 2048,
                                                   wlo + (size_t)l * 2048, ba + l * D, B,
                                                   rowptr, col, 1, N);
        // GEMM 2: plain, B -> A
        k_gemm_mma<<<gemm_blocks, 256, SMEM_MMA>>>(B, whi + (size_t)(5 + l) * 2048,
                                                   wlo + (size_t)(5 + l) * 2048, bb + l * D, A,
                                                   rowptr, col, 0, N);
    }

    k_pool_partial<<<NPART, 128>>>(A, part, N);
    k_final<<<1, 128>>>(part, Wlin, blin, out);
}

// round 12
// speedup vs baseline: 1.7696x; 1.7696x over previous
#include <cuda_runtime.h>
#include <cuda_bf16.h>
#include <cstdint>

// Problem constants
#define MAXN 100000
#define MAXE 600000
#define D 128
#define L_LAYERS 5
#define NPART 296
#define SCAN_BLK 1024

// ---------------- scratch (device globals; no allocation allowed) -------------
__device__ float g_bufA[MAXN * D];
__device__ float g_bufB[MAXN * D];
__device__ int   g_deg[MAXN];
__device__ int   g_rowptr[MAXN + 1];
__device__ int   g_cursor[MAXN];
__device__ int   g_col[MAXE];
__device__ float g_part[NPART * D];
__device__ int   g_bsum[128];
__device__ int   g_boff[128];
// pre-split transposed weights: 10 matrices x 128x128 bf16 (as uint4)
__device__ uint4 g_WhiT[10 * 128 * 128 / 8];
__device__ uint4 g_WloT[10 * 128 * 128 / 8];

// ---------------- utility kernels --------------------------------------------
__global__ void k_zero_int(int* __restrict__ p, int n) {
    int i = blockIdx.x * blockDim.x + threadIdx.x;
    if (i < n) p[i] = 0;
}

__global__ void k_gather(const int* __restrict__ x, const float* __restrict__ emb,
                         float* __restrict__ h, int n) {
    int i = blockIdx.x * blockDim.x + threadIdx.x;
    if (i < n * (D / 4)) {
        int node = i >> 5;
        int q    = i & 31;
        reinterpret_cast<float4*>(h)[(size_t)node * 32 + q] =
            reinterpret_cast<const float4*>(emb)[(size_t)x[node] * 32 + q];
    }
}

__global__ void k_count(const int* __restrict__ dst, int* __restrict__ deg, int e) {
    int i = blockIdx.x * blockDim.x + threadIdx.x;
    if (i < e) atomicAdd(&deg[dst[i]], 1);
}

// split + transpose weights: WT[n][k] = split(W[k][n]); 40 blocks (mat, k-quarter)
__global__ void k_wsplit(const float* __restrict__ Wa, const float* __restrict__ Wb,
                         __nv_bfloat16* __restrict__ hi, __nv_bfloat16* __restrict__ lo) {
    int mat = blockIdx.x >> 2, kq = blockIdx.x & 3;
    const float* W = (mat < 5) ? (Wa + mat * 16384) : (Wb + (mat - 5) * 16384);
    __nv_bfloat16* H  = hi + mat * 16384;
    __nv_bfloat16* Lo = lo + mat * 16384;
    int nidx = threadIdx.x;
    for (int k = kq * 32; k < kq * 32 + 32; k++) {
        float x = W[k * 128 + nidx];
        __nv_bfloat16 h = __float2bfloat16(x);
        H[nidx * 128 + k]  = h;
        Lo[nidx * 128 + k] = __float2bfloat16(x - __bfloat162float(h));
    }
}

// ---- 3-phase scan -------------------------------------------------------------
__global__ void k_scan_blk(const int* __restrict__ deg, int* __restrict__ rowptr,
                           int* __restrict__ bsum, int n) {
    int i = blockIdx.x * SCAN_BLK + threadIdx.x;
    int lane = threadIdx.x & 31, wid = threadIdx.x >> 5;
    int v = (i < n) ? deg[i] : 0;
    int inc = v;
#pragma unroll
    for (int o = 1; o < 32; o <<= 1) {
        int t = __shfl_up_sync(0xFFFFFFFFu, inc, o);
        if (lane >= o) inc += t;
    }
    __shared__ int wsum[32];
    if (lane == 31) wsum[wid] = inc;
    __syncthreads();
    if (wid == 0) {
        int s = wsum[lane];
#pragma unroll
        for (int o = 1; o < 32; o <<= 1) {
            int t = __shfl_up_sync(0xFFFFFFFFu, s, o);
            if (lane >= o) s += t;
        }
        wsum[lane] = s;
    }
    __syncthreads();
    int base = (wid > 0) ? wsum[wid - 1] : 0;
    if (i < n) rowptr[i] = base + inc - v;
    if (threadIdx.x == SCAN_BLK - 1) bsum[blockIdx.x] = base + inc;
}

__global__ void k_scan_top(const int* __restrict__ bsum, int* __restrict__ boff,
                           int* __restrict__ total_out, int nb) {
    int t = threadIdx.x, lane = t & 31, wid = t >> 5;
    int v = (t < nb) ? bsum[t] : 0;
    int inc = v;
#pragma unroll
    for (int o = 1; o < 32; o <<= 1) {
        int u = __shfl_up_sync(0xFFFFFFFFu, inc, o);
        if (lane >= o) inc += u;
    }
    __shared__ int ws[32];
    __shared__ int wsx[33];
    if (lane == 31) ws[wid] = inc;
    __syncthreads();
    if (t == 0) {
        wsx[0] = 0;
        for (int w = 0; w < 4; w++) wsx[w + 1] = wsx[w] + ws[w];
    }
    __syncthreads();
    int excl = wsx[wid] + inc - v;
    if (t < nb) boff[t] = excl;
    if (t == blockDim.x - 1) *total_out = wsx[4];
}

__global__ void k_scan_add(int* __restrict__ rowptr, int* __restrict__ cursor,
                           const int* __restrict__ boff, int n) {
    int i = blockIdx.x * blockDim.x + threadIdx.x;
    if (i < n) {
        int r = rowptr[i] + boff[i >> 10];
        rowptr[i] = r;
        cursor[i] = r;
    }
}

__global__ void k_scatter(const int* __restrict__ src, const int* __restrict__ dst,
                          int* __restrict__ cursor, int* __restrict__ col, int e) {
    int i = blockIdx.x * blockDim.x + threadIdx.x;
    if (i < e) {
        int d = dst[i];
        int p = atomicAdd(&cursor[d], 1);
        col[p] = src[i];
    }
}

// z[n,:] = h[n,:] + sum neighbors  (standalone, latency-tolerant)
__global__ void k_agg(const float* __restrict__ h, const int* __restrict__ rowptr,
                      const int* __restrict__ col, float* __restrict__ z, int n) {
    int node = blockIdx.x * 4 + (threadIdx.x >> 5);
    if (node >= n) return;
    int lane = threadIdx.x & 31;
    const float4* h4 = reinterpret_cast<const float4*>(h);
    float4 acc = h4[(size_t)node * 32 + lane];
    int s0 = rowptr[node], s1 = rowptr[node + 1];
    int j = s0;
    for (; j + 1 < s1; j += 2) {
        int c0 = __ldg(&col[j]), c1 = __ldg(&col[j + 1]);
        float4 v0 = __ldg(&h4[(size_t)c0 * 32 + lane]);
        float4 v1 = __ldg(&h4[(size_t)c1 * 32 + lane]);
        acc.x += v0.x + v1.x; acc.y += v0.y + v1.y;
        acc.z += v0.z + v1.z; acc.w += v0.w + v1.w;
    }
    if (j < s1) {
        int c = __ldg(&col[j]);
        float4 v = __ldg(&h4[(size_t)c * 32 + lane]);
        acc.x += v.x; acc.y += v.y; acc.z += v.z; acc.w += v.w;
    }
    reinterpret_cast<float4*>(z)[(size_t)node * 32 + lane] = acc;
}

// ---------------- fused 2-GEMM layer: h = relu(relu(z@Wa+ba)@Wb+bb) -----------
// Block tile 128 rows x 128 cols; 8 warps (4m x 2n), warp tile 32x64; K=128.
// Split-bf16: 3 HMMA terms per GEMM. SMEM bf16 row stride 272 B.
#define TSTR   272
#define SM_ZHI 0
#define SM_ZLO (128 * TSTR)                  // 34816
#define SM_WAHI (2 * 128 * TSTR)             // 69632
#define SM_WALO (SM_WAHI + 128 * TSTR)       // 104448
#define SM_WBHI (SM_WALO + 128 * TSTR)       // 139264
#define SM_WBLO (SM_WBHI + 128 * TSTR)       // 174080
#define SM_BA  (SM_WBLO + 128 * TSTR)        // 208896
#define SM_BB  (SM_BA + 512)                 // 209408
#define SMEM_L (SM_BB + 512)                 // 209920

__device__ __forceinline__ uint32_t smem_u32(const void* p) {
    uint32_t a;
    asm("{ .reg .u64 t; cvta.to.shared.u64 t, %1; cvt.u32.u64 %0, t; }" : "=r"(a) : "l"(p));
    return a;
}
__device__ __forceinline__ void ldsm_x4(uint32_t* r, uint32_t addr) {
    asm volatile("ldmatrix.sync.aligned.m8n8.x4.shared.b16 {%0,%1,%2,%3}, [%4];"
        : "=r"(r[0]), "=r"(r[1]), "=r"(r[2]), "=r"(r[3]) : "r"(addr));
}
__device__ __forceinline__ void mma_16816(float* c, const uint32_t* a, const uint32_t* b) {
    asm volatile(
        "mma.sync.aligned.m16n8k16.row.col.f32.bf16.bf16.f32 "
        "{%0,%1,%2,%3}, {%4,%5,%6,%7}, {%8,%9}, {%0,%1,%2,%3};"
        : "+f"(c[0]), "+f"(c[1]), "+f"(c[2]), "+f"(c[3])
        : "r"(a[0]), "r"(a[1]), "r"(a[2]), "r"(a[3]), "r"(b[0]), "r"(b[1]));
}
__device__ __forceinline__ uint32_t pack_bf16x2(float a, float b) {
    __nv_bfloat162 t = __floats2bfloat162_rn(a, b);
    return *reinterpret_cast<uint32_t*>(&t);
}
__device__ __forceinline__ void cp_async16(uint32_t saddr, const void* gptr) {
    asm volatile("cp.async.ca.shared.global [%0], [%1], 16;" :: "r"(saddr), "l"(gptr));
}

// One GEMM pass over the staged Z tiles against W tiles at (whi_ofs, wlo_ofs).
__device__ __forceinline__ void gemm_pass(uint32_t sb, uint32_t whi_ofs, uint32_t wlo_ofs,
                                          int lane, int m0, int n0, float acc[2][8][4]) {
#pragma unroll
    for (int a = 0; a < 2; a++)
#pragma unroll
        for (int b = 0; b < 8; b++)
#pragma unroll
            for (int c = 0; c < 4; c++) acc[a][b][c] = 0.f;

    const uint32_t a_row  = m0 + (lane & 15);
    const uint32_t a_coff = (lane >> 4) * 8;
    const uint32_t b_row  = n0 + ((lane >> 4) << 3) + (lane & 7);
    const uint32_t b_coff = ((lane >> 3) & 1) * 8;

#pragma unroll
    for (int ks = 0; ks < 8; ks++) {
        const int k = ks * 16;
        uint32_t ah[2][4], al[2][4];
#pragma unroll
        for (int mf = 0; mf < 2; mf++) {
            uint32_t addr = sb + SM_ZHI + (a_row + mf * 16) * TSTR + (k + a_coff) * 2;
            ldsm_x4(ah[mf], addr);
            ldsm_x4(al[mf], addr + (SM_ZLO - SM_ZHI));
        }
#pragma unroll
        for (int nfg = 0; nfg < 4; nfg++) {
            uint32_t baddr = sb + whi_ofs + (b_row + nfg * 16) * TSTR + (k + b_coff) * 2;
            uint32_t bh[4], bl[4];
            ldsm_x4(bh, baddr);
            ldsm_x4(bl, baddr + (wlo_ofs - whi_ofs));
#pragma unroll
            for (int mf = 0; mf < 2; mf++) {
                mma_16816(acc[mf][nfg * 2 + 0], ah[mf], bh + 0);
                mma_16816(acc[mf][nfg * 2 + 0], al[mf], bh + 0);
                mma_16816(acc[mf][nfg * 2 + 0], ah[mf], bl + 0);
                mma_16816(acc[mf][nfg * 2 + 1], ah[mf], bh + 2);
                mma_16816(acc[mf][nfg * 2 + 1], al[mf], bh + 2);
                mma_16816(acc[mf][nfg * 2 + 1], ah[mf], bl + 2);
            }
        }
    }
}

__global__ __launch_bounds__(256, 1)
void k_layer(const float* __restrict__ Z,
             const uint4* __restrict__ WaHi, const uint4* __restrict__ WaLo,
             const uint4* __restrict__ WbHi, const uint4* __restrict__ WbLo,
             const float* __restrict__ ba, const float* __restrict__ bb,
             float* __restrict__ C, int n) {
    extern __shared__ char sm[];
    const uint32_t sb = smem_u32(sm);
    const int tid = threadIdx.x;
    const int lane = tid & 31, w = tid >> 5;
    const int rowBase = blockIdx.x * 128;

    // ---- cp.async Wa (group 1), then Wb (group 0 pending) ----
#pragma unroll
    for (int it = 0; it < 8; it++) {
        int j = tid + it * 256;              // 0..2047
        int row = j >> 4, chunk = j & 15;
        uint32_t dofs = row * TSTR + chunk * 16;
        cp_async16(sb + SM_WAHI + dofs, WaHi + row * 16 + chunk);
        cp_async16(sb + SM_WALO + dofs, WaLo + row * 16 + chunk);
    }
    asm volatile("cp.async.commit_group;" ::: "memory");
#pragma unroll
    for (int it = 0; it < 8; it++) {
        int j = tid + it * 256;
        int row = j >> 4, chunk = j & 15;
        uint32_t dofs = row * TSTR + chunk * 16;
        cp_async16(sb + SM_WBHI + dofs, WbHi + row * 16 + chunk);
        cp_async16(sb + SM_WBLO + dofs, WbLo + row * 16 + chunk);
    }
    asm volatile("cp.async.commit_group;" ::: "memory");

    if (tid < 128) {
        reinterpret_cast<float*>(sm + SM_BA)[tid] = ba[tid];
        reinterpret_cast<float*>(sm + SM_BB)[tid] = bb[tid];
    }

    // ---- stage Z: thread = (row = tid>>1, half = tid&1), 16 float4 each ----
    {
        const int row = tid >> 1, half = tid & 1;
        const int gr = rowBase + row;
        const float4* zr = reinterpret_cast<const float4*>(Z + (size_t)gr * 128) + half * 16;
        char* zh = sm + SM_ZHI + row * TSTR + half * 128;
        char* zl = sm + SM_ZLO + row * TSTR + half * 128;
#pragma unroll
        for (int j = 0; j < 16; j++) {
            float4 v = (gr < n) ? __ldg(&zr[j]) : make_float4(0.f, 0.f, 0.f, 0.f);
            uint2 hp, lp;
            hp.x = pack_bf16x2(v.x, v.y);
            hp.y = pack_bf16x2(v.z, v.w);
            float lx = v.x - __bfloat162float(__float2bfloat16(v.x));
            float ly = v.y - __bfloat162float(__float2bfloat16(v.y));
            float lz = v.z - __bfloat162float(__float2bfloat16(v.z));
            float lw = v.w - __bfloat162float(__float2bfloat16(v.w));
            lp.x = pack_bf16x2(lx, ly);
            lp.y = pack_bf16x2(lz, lw);
            reinterpret_cast<uint2*>(zh)[j] = hp;
            reinterpret_cast<uint2*>(zl)[j] = lp;
        }
    }
    asm volatile("cp.async.wait_group 1;" ::: "memory");   // Wa resident
    __syncthreads();

    const int m0 = (w >> 1) * 32, n0 = (w & 1) * 64;
    float acc[2][8][4];

    // ---- phase 1: acc1 = Z @ Wa ----
    gemm_pass(sb, SM_WAHI, SM_WALO, lane, m0, n0, acc);
    __syncthreads();                                       // all ldsm of Z done

    // ---- relu(acc1+ba) -> Z smem (bf16 hi/lo), each warp its own quadrant ----
    {
        const float* bav = reinterpret_cast<const float*>(sm + SM_BA);
#pragma unroll
        for (int mf = 0; mf < 2; mf++) {
#pragma unroll
            for (int nf = 0; nf < 8; nf++) {
                int r = m0 + mf * 16 + (lane >> 2);
                int c = n0 + nf * 8 + (lane & 3) * 2;
                float b0 = bav[c], b1 = bav[c + 1];
                float z0 = fmaxf(acc[mf][nf][0] + b0, 0.f);
                float z1 = fmaxf(acc[mf][nf][1] + b1, 0.f);
                float z2 = fmaxf(acc[mf][nf][2] + b0, 0.f);
                float z3 = fmaxf(acc[mf][nf][3] + b1, 0.f);
                float h0 = __bfloat162float(__float2bfloat16(z0));
                float h1 = __bfloat162float(__float2bfloat16(z1));
                float h2 = __bfloat162float(__float2bfloat16(z2));
                float h3 = __bfloat162float(__float2bfloat16(z3));
                *reinterpret_cast<uint32_t*>(sm + SM_ZHI + r * TSTR + c * 2) =
                    pack_bf16x2(z0, z1);
                *reinterpret_cast<uint32_t*>(sm + SM_ZLO + r * TSTR + c * 2) =
                    pack_bf16x2(z0 - h0, z1 - h1);
                *reinterpret_cast<uint32_t*>(sm + SM_ZHI + (r + 8) * TSTR + c * 2) =
                    pack_bf16x2(z2, z3);
                *reinterpret_cast<uint32_t*>(sm + SM_ZLO + (r + 8) * TSTR + c * 2) =
                    pack_bf16x2(z2 - h2, z3 - h3);
            }
        }
    }
    asm volatile("cp.async.wait_group 0;" ::: "memory");   // Wb resident
    __syncthreads();

    // ---- phase 2: acc2 = Z' @ Wb ----
    gemm_pass(sb, SM_WBHI, SM_WBLO, lane, m0, n0, acc);

    // ---- epilogue: relu(acc2+bb) -> global fp32 ----
    {
        const float* bbv = reinterpret_cast<const float*>(sm + SM_BB);
#pragma unroll
        for (int mf = 0; mf < 2; mf++) {
#pragma unroll
            for (int nf = 0; nf < 8; nf++) {
                int r = m0 + mf * 16 + (lane >> 2);
                int c = n0 + nf * 8 + (lane & 3) * 2;
                float b0 = bbv[c], b1 = bbv[c + 1];
                int gr0 = rowBase + r;
                if (gr0 < n) {
                    float2 v;
                    v.x = fmaxf(acc[mf][nf][0] + b0, 0.f);
                    v.y = fmaxf(acc[mf][nf][1] + b1, 0.f);
                    *reinterpret_cast<float2*>(C + (size_t)gr0 * 128 + c) = v;
                }
                int gr1 = gr0 + 8;
                if (gr1 < n) {
                    float2 v;
                    v.x = fmaxf(acc[mf][nf][2] + b0, 0.f);
                    v.y = fmaxf(acc[mf][nf][3] + b1, 0.f);
                    *reinterpret_cast<float2*>(C + (size_t)gr1 * 128 + c) = v;
                }
            }
        }
    }
}

// ---------------- pool + final -------------------------------------------------
__global__ void k_pool_partial(const float* __restrict__ h, float* __restrict__ part, int n) {
    int d = threadIdx.x;
    float acc = 0.f;
    for (int r = blockIdx.x; r < n; r += gridDim.x)
        acc += h[(size_t)r * D + d];
    part[blockIdx.x * D + d] = acc;
}

__global__ void k_final(const float* __restrict__ part, const float* __restrict__ Wlin,
                        const float* __restrict__ blin, float* __restrict__ out) {
    __shared__ float pooled[D];
    int t = threadIdx.x;
    float acc = 0.f;
    for (int p = 0; p < NPART; p++) acc += part[p * D + t];
    pooled[t] = acc;
    __syncthreads();
    float o = blin[t];
    for (int d = 0; d < D; d++) o = fmaf(pooled[d], Wlin[d * D + t], o);
    out[t] = o;
}

// ---------------- launch -------------------------------------------------------
extern "C" void kernel_launch(void* const* d_in, const int* in_sizes, int n_in,
                              void* d_out, int out_size) {
    const int*   x    = (const int*)d_in[0];
    const int*   ei   = (const int*)d_in[1];
    const float* emb  = (const float*)d_in[2];
    const float* Wa   = (const float*)d_in[3];
    const float* ba   = (const float*)d_in[4];
    const float* Wb   = (const float*)d_in[5];
    const float* bb   = (const float*)d_in[6];
    const float* Wlin = (const float*)d_in[7];
    const float* blin = (const float*)d_in[8];
    float* out = (float*)d_out;

    const int N = in_sizes[0];
    const int E = in_sizes[1] / 2;
    const int* src = ei;
    const int* dst = ei + E;

    float *A, *B, *part;
    int *deg, *rowptr, *cursor, *col, *bsum, *boff;
    uint4 *whi, *wlo;
    cudaGetSymbolAddress((void**)&A, g_bufA);
    cudaGetSymbolAddress((void**)&B, g_bufB);
    cudaGetSymbolAddress((void**)&deg, g_deg);
    cudaGetSymbolAddress((void**)&rowptr, g_rowptr);
    cudaGetSymbolAddress((void**)&cursor, g_cursor);
    cudaGetSymbolAddress((void**)&col, g_col);
    cudaGetSymbolAddress((void**)&part, g_part);
    cudaGetSymbolAddress((void**)&bsum, g_bsum);
    cudaGetSymbolAddress((void**)&boff, g_boff);
    cudaGetSymbolAddress((void**)&whi, g_WhiT);
    cudaGetSymbolAddress((void**)&wlo, g_WloT);

    cudaFuncSetAttribute(k_layer, cudaFuncAttributeMaxDynamicSharedMemorySize, SMEM_L);

    // h = emb[x]
    k_gather<<<(N * 32 + 255) / 256, 256>>>(x, emb, A, N);

    // pre-split weights to transposed bf16 hi/lo
    k_wsplit<<<40, 128>>>(Wa, Wb, (__nv_bfloat16*)whi, (__nv_bfloat16*)wlo);

    // CSR build
    k_zero_int<<<(N + 255) / 256, 256>>>(deg, N);
    k_count<<<(E + 255) / 256, 256>>>(dst, deg, E);
    const int nb = (N + SCAN_BLK - 1) / SCAN_BLK;
    k_scan_blk<<<nb, SCAN_BLK>>>(deg, rowptr, bsum, N);
    k_scan_top<<<1, 128>>>(bsum, boff, rowptr + N, nb);
    k_scan_add<<<(N + 255) / 256, 256>>>(rowptr, cursor, boff, N);
    k_scatter<<<(E + 255) / 256, 256>>>(src, dst, cursor, col, E);

    const int layer_blocks = (N + 127) / 128;
    const int agg_blocks   = (N + 3) / 4;
    for (int l = 0; l < L_LAYERS; l++) {
        k_agg<<<agg_blocks, 128>>>(A, rowptr, col, B, N);           // B = A + agg(A)
        k_layer<<<layer_blocks, 256, SMEM_L>>>(B,
            whi + (size_t)l * 2048, wlo + (size_t)l * 2048,
            whi + (size_t)(5 + l) * 2048, wlo + (size_t)(5 + l) * 2048,
            ba + l * D, bb + l * D, A, N);                           // A = layer(B)
    }

    k_pool_partial<<<NPART, 128>>>(A, part, N);
    k_final<<<1, 128>>>(part, Wlin, blin, out);
}

// round 13
// speedup vs baseline: 2.0935x; 1.1830x over previous
#include <cuda_runtime.h>
#include <cuda_bf16.h>
#include <cstdint>

// Problem constants
#define MAXN 100000
#define MAXE 600000
#define D 128
#define L_LAYERS 5
#define NPART 296
#define SCAN_BLK 1024

// ---------------- scratch (device globals; no allocation allowed) -------------
__device__ float g_bufA[MAXN * D];
// aggregated z in split-bf16 (padded by 128 rows so tail-tile cp.async stays in-bounds)
__device__ __align__(16) __nv_bfloat16 g_zhi[(MAXN + 128) * D];
__device__ __align__(16) __nv_bfloat16 g_zlo[(MAXN + 128) * D];
__device__ int   g_deg[MAXN];
__device__ int   g_rowptr[MAXN + 1];
__device__ int   g_cursor[MAXN];
__device__ int   g_col[MAXE];
__device__ float g_part[NPART * D];
__device__ int   g_bsum[128];
__device__ int   g_boff[128];
// pre-split transposed weights: 10 matrices x 128x128 bf16 (as uint4)
__device__ uint4 g_WhiT[10 * 128 * 128 / 8];
__device__ uint4 g_WloT[10 * 128 * 128 / 8];

// ---------------- utility kernels --------------------------------------------
__global__ void k_zero_int(int* __restrict__ p, int n) {
    int i = blockIdx.x * blockDim.x + threadIdx.x;
    if (i < n) p[i] = 0;
}

__global__ void k_gather(const int* __restrict__ x, const float* __restrict__ emb,
                         float* __restrict__ h, int n) {
    int i = blockIdx.x * blockDim.x + threadIdx.x;
    if (i < n * (D / 4)) {
        int node = i >> 5;
        int q    = i & 31;
        reinterpret_cast<float4*>(h)[(size_t)node * 32 + q] =
            reinterpret_cast<const float4*>(emb)[(size_t)x[node] * 32 + q];
    }
}

__global__ void k_count(const int* __restrict__ dst, int* __restrict__ deg, int e) {
    int i = blockIdx.x * blockDim.x + threadIdx.x;
    if (i < e) atomicAdd(&deg[dst[i]], 1);
}

// split + transpose weights: WT[n][k] = split(W[k][n]); 40 blocks (mat, k-quarter)
__global__ void k_wsplit(const float* __restrict__ Wa, const float* __restrict__ Wb,
                         __nv_bfloat16* __restrict__ hi, __nv_bfloat16* __restrict__ lo) {
    int mat = blockIdx.x >> 2, kq = blockIdx.x & 3;
    const float* W = (mat < 5) ? (Wa + mat * 16384) : (Wb + (mat - 5) * 16384);
    __nv_bfloat16* H  = hi + mat * 16384;
    __nv_bfloat16* Lo = lo + mat * 16384;
    int nidx = threadIdx.x;
    for (int k = kq * 32; k < kq * 32 + 32; k++) {
        float x = W[k * 128 + nidx];
        __nv_bfloat16 h = __float2bfloat16(x);
        H[nidx * 128 + k]  = h;
        Lo[nidx * 128 + k] = __float2bfloat16(x - __bfloat162float(h));
    }
}

// ---- 3-phase scan -------------------------------------------------------------
__global__ void k_scan_blk(const int* __restrict__ deg, int* __restrict__ rowptr,
                           int* __restrict__ bsum, int n) {
    int i = blockIdx.x * SCAN_BLK + threadIdx.x;
    int lane = threadIdx.x & 31, wid = threadIdx.x >> 5;
    int v = (i < n) ? deg[i] : 0;
    int inc = v;
#pragma unroll
    for (int o = 1; o < 32; o <<= 1) {
        int t = __shfl_up_sync(0xFFFFFFFFu, inc, o);
        if (lane >= o) inc += t;
    }
    __shared__ int wsum[32];
    if (lane == 31) wsum[wid] = inc;
    __syncthreads();
    if (wid == 0) {
        int s = wsum[lane];
#pragma unroll
        for (int o = 1; o < 32; o <<= 1) {
            int t = __shfl_up_sync(0xFFFFFFFFu, s, o);
            if (lane >= o) s += t;
        }
        wsum[lane] = s;
    }
    __syncthreads();
    int base = (wid > 0) ? wsum[wid - 1] : 0;
    if (i < n) rowptr[i] = base + inc - v;
    if (threadIdx.x == SCAN_BLK - 1) bsum[blockIdx.x] = base + inc;
}

__global__ void k_scan_top(const int* __restrict__ bsum, int* __restrict__ boff,
                           int* __restrict__ total_out, int nb) {
    int t = threadIdx.x, lane = t & 31, wid = t >> 5;
    int v = (t < nb) ? bsum[t] : 0;
    int inc = v;
#pragma unroll
    for (int o = 1; o < 32; o <<= 1) {
        int u = __shfl_up_sync(0xFFFFFFFFu, inc, o);
        if (lane >= o) inc += u;
    }
    __shared__ int ws[32];
    __shared__ int wsx[33];
    if (lane == 31) ws[wid] = inc;
    __syncthreads();
    if (t == 0) {
        wsx[0] = 0;
        for (int w = 0; w < 4; w++) wsx[w + 1] = wsx[w] + ws[w];
    }
    __syncthreads();
    int excl = wsx[wid] + inc - v;
    if (t < nb) boff[t] = excl;
    if (t == blockDim.x - 1) *total_out = wsx[4];
}

__global__ void k_scan_add(int* __restrict__ rowptr, int* __restrict__ cursor,
                           const int* __restrict__ boff, int n) {
    int i = blockIdx.x * blockDim.x + threadIdx.x;
    if (i < n) {
        int r = rowptr[i] + boff[i >> 10];
        rowptr[i] = r;
        cursor[i] = r;
    }
}

__global__ void k_scatter(const int* __restrict__ src, const int* __restrict__ dst,
                          int* __restrict__ cursor, int* __restrict__ col, int e) {
    int i = blockIdx.x * blockDim.x + threadIdx.x;
    if (i < e) {
        int d = dst[i];
        int p = atomicAdd(&cursor[d], 1);
        col[p] = src[i];
    }
}

__device__ __forceinline__ uint32_t pack_bf16x2(float a, float b) {
    __nv_bfloat162 t = __floats2bfloat162_rn(a, b);
    return *reinterpret_cast<uint32_t*>(&t);
}

// z = h + sum neighbors, emitted directly as split-bf16 hi/lo.
// 8 nodes per 256-thread block; bandwidth-bound so the conversion ALU is free.
__global__ void k_agg(const float* __restrict__ h, const int* __restrict__ rowptr,
                      const int* __restrict__ col,
                      __nv_bfloat16* __restrict__ zhi, __nv_bfloat16* __restrict__ zlo,
                      int n) {
    int node = blockIdx.x * 8 + (threadIdx.x >> 5);
    if (node >= n) return;
    int lane = threadIdx.x & 31;
    const float4* h4 = reinterpret_cast<const float4*>(h);
    float4 acc = h4[(size_t)node * 32 + lane];
    int s0 = rowptr[node], s1 = rowptr[node + 1];
    int j = s0;
    for (; j + 1 < s1; j += 2) {
        int c0 = __ldg(&col[j]), c1 = __ldg(&col[j + 1]);
        float4 v0 = __ldg(&h4[(size_t)c0 * 32 + lane]);
        float4 v1 = __ldg(&h4[(size_t)c1 * 32 + lane]);
        acc.x += v0.x + v1.x; acc.y += v0.y + v1.y;
        acc.z += v0.z + v1.z; acc.w += v0.w + v1.w;
    }
    if (j < s1) {
        int c = __ldg(&col[j]);
        float4 v = __ldg(&h4[(size_t)c * 32 + lane]);
        acc.x += v.x; acc.y += v.y; acc.z += v.z; acc.w += v.w;
    }
    uint2 hp, lp;
    hp.x = pack_bf16x2(acc.x, acc.y);
    hp.y = pack_bf16x2(acc.z, acc.w);
    float hx = __bfloat162float(__float2bfloat16(acc.x));
    float hy = __bfloat162float(__float2bfloat16(acc.y));
    float hz = __bfloat162float(__float2bfloat16(acc.z));
    float hw = __bfloat162float(__float2bfloat16(acc.w));
    lp.x = pack_bf16x2(acc.x - hx, acc.y - hy);
    lp.y = pack_bf16x2(acc.z - hz, acc.w - hw);
    reinterpret_cast<uint2*>(zhi)[(size_t)node * 32 + lane] = hp;
    reinterpret_cast<uint2*>(zlo)[(size_t)node * 32 + lane] = lp;
}

// ---------------- fused 2-GEMM layer: h = relu(relu(z@Wa+ba)@Wb+bb) -----------
// Block tile 128 rows x 128 cols; 8 warps (4m x 2n), warp tile 32x64; K=128.
// Z arrives pre-split (bf16 hi/lo) -> staging is pure cp.async.
#define TSTR   272
#define SM_ZHI 0
#define SM_ZLO (128 * TSTR)                  // 34816
#define SM_WAHI (2 * 128 * TSTR)             // 69632
#define SM_WALO (SM_WAHI + 128 * TSTR)       // 104448
#define SM_WBHI (SM_WALO + 128 * TSTR)       // 139264
#define SM_WBLO (SM_WBHI + 128 * TSTR)       // 174080
#define SM_BA  (SM_WBLO + 128 * TSTR)        // 208896
#define SM_BB  (SM_BA + 512)                 // 209408
#define SMEM_L (SM_BB + 512)                 // 209920

__device__ __forceinline__ uint32_t smem_u32(const void* p) {
    uint32_t a;
    asm("{ .reg .u64 t; cvta.to.shared.u64 t, %1; cvt.u32.u64 %0, t; }" : "=r"(a) : "l"(p));
    return a;
}
__device__ __forceinline__ void ldsm_x4(uint32_t* r, uint32_t addr) {
    asm volatile("ldmatrix.sync.aligned.m8n8.x4.shared.b16 {%0,%1,%2,%3}, [%4];"
        : "=r"(r[0]), "=r"(r[1]), "=r"(r[2]), "=r"(r[3]) : "r"(addr));
}
__device__ __forceinline__ void mma_16816(float* c, const uint32_t* a, const uint32_t* b) {
    asm volatile(
        "mma.sync.aligned.m16n8k16.row.col.f32.bf16.bf16.f32 "
        "{%0,%1,%2,%3}, {%4,%5,%6,%7}, {%8,%9}, {%0,%1,%2,%3};"
        : "+f"(c[0]), "+f"(c[1]), "+f"(c[2]), "+f"(c[3])
        : "r"(a[0]), "r"(a[1]), "r"(a[2]), "r"(a[3]), "r"(b[0]), "r"(b[1]));
}
__device__ __forceinline__ void cp_async16(uint32_t saddr, const void* gptr) {
    asm volatile("cp.async.ca.shared.global [%0], [%1], 16;" :: "r"(saddr), "l"(gptr));
}

// One GEMM pass over the staged Z tiles against W tiles at (whi_ofs, wlo_ofs).
__device__ __forceinline__ void gemm_pass(uint32_t sb, uint32_t whi_ofs, uint32_t wlo_ofs,
                                          int lane, int m0, int n0, float acc[2][8][4]) {
#pragma unroll
    for (int a = 0; a < 2; a++)
#pragma unroll
        for (int b = 0; b < 8; b++)
#pragma unroll
            for (int c = 0; c < 4; c++) acc[a][b][c] = 0.f;

    const uint32_t a_row  = m0 + (lane & 15);
    const uint32_t a_coff = (lane >> 4) * 8;
    const uint32_t b_row  = n0 + ((lane >> 4) << 3) + (lane & 7);
    const uint32_t b_coff = ((lane >> 3) & 1) * 8;

#pragma unroll
    for (int ks = 0; ks < 8; ks++) {
        const int k = ks * 16;
        uint32_t ah[2][4], al[2][4];
#pragma unroll
        for (int mf = 0; mf < 2; mf++) {
            uint32_t addr = sb + SM_ZHI + (a_row + mf * 16) * TSTR + (k + a_coff) * 2;
            ldsm_x4(ah[mf], addr);
            ldsm_x4(al[mf], addr + (SM_ZLO - SM_ZHI));
        }
#pragma unroll
        for (int nfg = 0; nfg < 4; nfg++) {
            uint32_t baddr = sb + whi_ofs + (b_row + nfg * 16) * TSTR + (k + b_coff) * 2;
            uint32_t bh[4], bl[4];
            ldsm_x4(bh, baddr);
            ldsm_x4(bl, baddr + (wlo_ofs - whi_ofs));
#pragma unroll
            for (int mf = 0; mf < 2; mf++) {
                mma_16816(acc[mf][nfg * 2 + 0], ah[mf], bh + 0);
                mma_16816(acc[mf][nfg * 2 + 0], al[mf], bh + 0);
                mma_16816(acc[mf][nfg * 2 + 0], ah[mf], bl + 0);
                mma_16816(acc[mf][nfg * 2 + 1], ah[mf], bh + 2);
                mma_16816(acc[mf][nfg * 2 + 1], al[mf], bh + 2);
                mma_16816(acc[mf][nfg * 2 + 1], ah[mf], bl + 2);
            }
        }
    }
}

__global__ __launch_bounds__(256, 1)
void k_layer(const uint4* __restrict__ Zhi, const uint4* __restrict__ Zlo,
             const uint4* __restrict__ WaHi, const uint4* __restrict__ WaLo,
             const uint4* __restrict__ WbHi, const uint4* __restrict__ WbLo,
             const float* __restrict__ ba, const float* __restrict__ bb,
             float* __restrict__ C, int n) {
    extern __shared__ char sm[];
    const uint32_t sb = smem_u32(sm);
    const int tid = threadIdx.x;
    const int lane = tid & 31, w = tid >> 5;
    const int rowBase = blockIdx.x * 128;

    // ---- group 0: Z tiles + Wa (everything phase 1 needs), all cp.async ----
#pragma unroll
    for (int it = 0; it < 8; it++) {
        int j = tid + it * 256;              // 0..2047
        int row = j >> 4, chunk = j & 15;
        uint32_t dofs = row * TSTR + chunk * 16;
        size_t gofs = (size_t)(rowBase + row) * 16 + chunk;
        cp_async16(sb + SM_ZHI + dofs, Zhi + gofs);
        cp_async16(sb + SM_ZLO + dofs, Zlo + gofs);
    }
#pragma unroll
    for (int it = 0; it < 8; it++) {
        int j = tid + it * 256;
        int row = j >> 4, chunk = j & 15;
        uint32_t dofs = row * TSTR + chunk * 16;
        cp_async16(sb + SM_WAHI + dofs, WaHi + row * 16 + chunk);
        cp_async16(sb + SM_WALO + dofs, WaLo + row * 16 + chunk);
    }
    asm volatile("cp.async.commit_group;" ::: "memory");

    // ---- group 1: Wb (hidden under phase-1 compute) ----
#pragma unroll
    for (int it = 0; it < 8; it++) {
        int j = tid + it * 256;
        int row = j >> 4, chunk = j & 15;
        uint32_t dofs = row * TSTR + chunk * 16;
        cp_async16(sb + SM_WBHI + dofs, WbHi + row * 16 + chunk);
        cp_async16(sb + SM_WBLO + dofs, WbLo + row * 16 + chunk);
    }
    asm volatile("cp.async.commit_group;" ::: "memory");

    if (tid < 128) {
        reinterpret_cast<float*>(sm + SM_BA)[tid] = ba[tid];
        reinterpret_cast<float*>(sm + SM_BB)[tid] = bb[tid];
    }

    asm volatile("cp.async.wait_group 1;" ::: "memory");   // Z + Wa resident
    __syncthreads();

    const int m0 = (w >> 1) * 32, n0 = (w & 1) * 64;
    float acc[2][8][4];

    // ---- phase 1: acc1 = Z @ Wa ----
    gemm_pass(sb, SM_WAHI, SM_WALO, lane, m0, n0, acc);
    __syncthreads();                                       // all ldsm of Z done

    // ---- relu(acc1+ba) -> Z smem (bf16 hi/lo), each warp its own quadrant ----
    {
        const float* bav = reinterpret_cast<const float*>(sm + SM_BA);
#pragma unroll
        for (int mf = 0; mf < 2; mf++) {
#pragma unroll
            for (int nf = 0; nf < 8; nf++) {
                int r = m0 + mf * 16 + (lane >> 2);
                int c = n0 + nf * 8 + (lane & 3) * 2;
                float b0 = bav[c], b1 = bav[c + 1];
                float z0 = fmaxf(acc[mf][nf][0] + b0, 0.f);
                float z1 = fmaxf(acc[mf][nf][1] + b1, 0.f);
                float z2 = fmaxf(acc[mf][nf][2] + b0, 0.f);
                float z3 = fmaxf(acc[mf][nf][3] + b1, 0.f);
                float h0 = __bfloat162float(__float2bfloat16(z0));
                float h1 = __bfloat162float(__float2bfloat16(z1));
                float h2 = __bfloat162float(__float2bfloat16(z2));
                float h3 = __bfloat162float(__float2bfloat16(z3));
                *reinterpret_cast<uint32_t*>(sm + SM_ZHI + r * TSTR + c * 2) =
                    pack_bf16x2(z0, z1);
                *reinterpret_cast<uint32_t*>(sm + SM_ZLO + r * TSTR + c * 2) =
                    pack_bf16x2(z0 - h0, z1 - h1);
                *reinterpret_cast<uint32_t*>(sm + SM_ZHI + (r + 8) * TSTR + c * 2) =
                    pack_bf16x2(z2, z3);
                *reinterpret_cast<uint32_t*>(sm + SM_ZLO + (r + 8) * TSTR + c * 2) =
                    pack_bf16x2(z2 - h2, z3 - h3);
            }
        }
    }
    asm volatile("cp.async.wait_group 0;" ::: "memory");   // Wb resident
    __syncthreads();

    // ---- phase 2: acc2 = Z' @ Wb ----
    gemm_pass(sb, SM_WBHI, SM_WBLO, lane, m0, n0, acc);

    // ---- epilogue: relu(acc2+bb) -> global fp32 ----
    {
        const float* bbv = reinterpret_cast<const float*>(sm + SM_BB);
#pragma unroll
        for (int mf = 0; mf < 2; mf++) {
#pragma unroll
            for (int nf = 0; nf < 8; nf++) {
                int r = m0 + mf * 16 + (lane >> 2);
                int c = n0 + nf * 8 + (lane & 3) * 2;
                float b0 = bbv[c], b1 = bbv[c + 1];
                int gr0 = rowBase + r;
                if (gr0 < n) {
                    float2 v;
                    v.x = fmaxf(acc[mf][nf][0] + b0, 0.f);
                    v.y = fmaxf(acc[mf][nf][1] + b1, 0.f);
                    *reinterpret_cast<float2*>(C + (size_t)gr0 * 128 + c) = v;
                }
                int gr1 = gr0 + 8;
                if (gr1 < n) {
                    float2 v;
                    v.x = fmaxf(acc[mf][nf][2] + b0, 0.f);
                    v.y = fmaxf(acc[mf][nf][3] + b1, 0.f);
                    *reinterpret_cast<float2*>(C + (size_t)gr1 * 128 + c) = v;
                }
            }
        }
    }
}

// ---------------- pool + final -------------------------------------------------
__global__ void k_pool_partial(const float* __restrict__ h, float* __restrict__ part, int n) {
    int d = threadIdx.x;
    float acc = 0.f;
    for (int r = blockIdx.x; r < n; r += gridDim.x)
        acc += h[(size_t)r * D + d];
    part[blockIdx.x * D + d] = acc;
}

__global__ void k_final(const float* __restrict__ part, const float* __restrict__ Wlin,
                        const float* __restrict__ blin, float* __restrict__ out) {
    __shared__ float pooled[D];
    int t = threadIdx.x;
    float acc = 0.f;
    for (int p = 0; p < NPART; p++) acc += part[p * D + t];
    pooled[t] = acc;
    __syncthreads();
    float o = blin[t];
    for (int d = 0; d < D; d++) o = fmaf(pooled[d], Wlin[d * D + t], o);
    out[t] = o;
}

// ---------------- launch -------------------------------------------------------
extern "C" void kernel_launch(void* const* d_in, const int* in_sizes, int n_in,
                              void* d_out, int out_size) {
    const int*   x    = (const int*)d_in[0];
    const int*   ei   = (const int*)d_in[1];
    const float* emb  = (const float*)d_in[2];
    const float* Wa   = (const float*)d_in[3];
    const float* ba   = (const float*)d_in[4];
    const float* Wb   = (const float*)d_in[5];
    const float* bb   = (const float*)d_in[6];
    const float* Wlin = (const float*)d_in[7];
    const float* blin = (const float*)d_in[8];
    float* out = (float*)d_out;

    const int N = in_sizes[0];
    const int E = in_sizes[1] / 2;
    const int* src = ei;
    const int* dst = ei + E;

    float *A, *part;
    __nv_bfloat16 *zhi, *zlo;
    int *deg, *rowptr, *cursor, *col, *bsum, *boff;
    uint4 *whi, *wlo;
    cudaGetSymbolAddress((void**)&A, g_bufA);
    cudaGetSymbolAddress((void**)&zhi, g_zhi);
    cudaGetSymbolAddress((void**)&zlo, g_zlo);
    cudaGetSymbolAddress((void**)&deg, g_deg);
    cudaGetSymbolAddress((void**)&rowptr, g_rowptr);
    cudaGetSymbolAddress((void**)&cursor, g_cursor);
    cudaGetSymbolAddress((void**)&col, g_col);
    cudaGetSymbolAddress((void**)&part, g_part);
    cudaGetSymbolAddress((void**)&bsum, g_bsum);
    cudaGetSymbolAddress((void**)&boff, g_boff);
    cudaGetSymbolAddress((void**)&whi, g_WhiT);
    cudaGetSymbolAddress((void**)&wlo, g_WloT);

    cudaFuncSetAttribute(k_layer, cudaFuncAttributeMaxDynamicSharedMemorySize, SMEM_L);

    // h = emb[x]
    k_gather<<<(N * 32 + 255) / 256, 256>>>(x, emb, A, N);

    // pre-split weights to transposed bf16 hi/lo
    k_wsplit<<<40, 128>>>(Wa, Wb, (__nv_bfloat16*)whi, (__nv_bfloat16*)wlo);

    // CSR build
    k_zero_int<<<(N + 255) / 256, 256>>>(deg, N);
    k_count<<<(E + 255) / 256, 256>>>(dst, deg, E);
    const int nb = (N + SCAN_BLK - 1) / SCAN_BLK;
    k_scan_blk<<<nb, SCAN_BLK>>>(deg, rowptr, bsum, N);
    k_scan_top<<<1, 128>>>(bsum, boff, rowptr + N, nb);
    k_scan_add<<<(N + 255) / 256, 256>>>(rowptr, cursor, boff, N);
    k_scatter<<<(E + 255) / 256, 256>>>(src, dst, cursor, col, E);

    const int layer_blocks = (N + 127) / 128;
    const int agg_blocks   = (N + 7) / 8;
    for (int l = 0; l < L_LAYERS; l++) {
        // z = h + agg(h), emitted as split-bf16
        k_agg<<<agg_blocks, 256>>>(A, rowptr, col, zhi, zlo, N);
        // h = relu(relu(z@Wa+ba)@Wb+bb)
        k_layer<<<layer_blocks, 256, SMEM_L>>>(
            (const uint4*)zhi, (const uint4*)zlo,
            whi + (size_t)l * 2048, wlo + (size_t)l * 2048,
            whi + (size_t)(5 + l) * 2048, wlo + (size_t)(5 + l) * 2048,
            ba + l * D, bb + l * D, A, N);
    }

    k_pool_partial<<<NPART, 128>>>(A, part, N);
    k_final<<<1, 128>>>(part, Wlin, blin, out);
}